// round 2
// baseline (speedup 1.0000x reference)
#include <cuda_runtime.h>

#define T_LEN 4096
#define NTH   256
#define PER   (T_LEN / NTH)

#define DTF   (1.0f / 200.0f)
#define DT2H  (DTF * DTF * 0.5f)

// Build per-step rotation via Rodrigues with Taylor sin/cos (theta <= ~0.03):
// R = I + A*K(w) + B*(w w^T - |w|^2 I)
// A = dt*(1 - th2/6 + th2^2/120), B = dt^2*(1/2 - th2/24 + th2^2/720), th2 = |w|^2 dt^2
__device__ __forceinline__ void make_Rk(float wx, float wy, float wz, float* Rk) {
    float n2  = fmaf(wx, wx, fmaf(wy, wy, wz * wz));
    float th2 = n2 * (DTF * DTF);
    float A   = DTF * (1.0f + th2 * (-1.0f / 6.0f + th2 * (1.0f / 120.0f)));
    float Bc  = (DTF * DTF) * (0.5f + th2 * (-1.0f / 24.0f + th2 * (1.0f / 720.0f)));
    float xy = wx * wy, xz = wx * wz, yz = wy * wz;
    Rk[0] = 1.0f + Bc * (wx * wx - n2);
    Rk[1] = Bc * xy - A * wz;
    Rk[2] = Bc * xz + A * wy;
    Rk[3] = Bc * xy + A * wz;
    Rk[4] = 1.0f + Bc * (wy * wy - n2);
    Rk[5] = Bc * yz - A * wx;
    Rk[6] = Bc * xz - A * wy;
    Rk[7] = Bc * yz + A * wx;
    Rk[8] = 1.0f + Bc * (wz * wz - n2);
}

__global__ void __launch_bounds__(NTH)
preint_kernel(const float* __restrict__ in, float* __restrict__ out) {
    // scan storage: 16 floats per thread element (R9, v3, p3, ndt), pad to 17 (conflict-free)
    __shared__ float sc[NTH][17];

    const int b   = blockIdx.x;
    const int tid = threadIdx.x;

    const float* rp0 = in + ((size_t)b * T_LEN + (size_t)tid * PER) * 6;

    // ---------------- Phase 1: thread-local aggregate (recurrence from identity) -------------
    float R0 = 1.f, R1 = 0.f, R2 = 0.f,
          R3 = 0.f, R4 = 1.f, R5 = 0.f,
          R6 = 0.f, R7 = 0.f, R8 = 1.f;
    float vx = 0.f, vy = 0.f, vz = 0.f;
    float px = 0.f, py = 0.f, pz = 0.f;

    {
        const float* rp = rp0;
#pragma unroll 2
        for (int k = 0; k < PER; k++) {
            float2 c0 = *(const float2*)(rp);
            float2 c1 = *(const float2*)(rp + 2);
            float2 c2 = *(const float2*)(rp + 4);
            rp += 6;
            float wx = c0.x, wy = c0.y, wz = c1.x;
            float ax = c1.y, ay = c2.x, az = c2.y;

            float Rk[9];
            make_Rk(wx, wy, wz, Rk);

            // R = R * Rk
            float n0 = R0 * Rk[0] + R1 * Rk[3] + R2 * Rk[6];
            float n1 = R0 * Rk[1] + R1 * Rk[4] + R2 * Rk[7];
            float n2 = R0 * Rk[2] + R1 * Rk[5] + R2 * Rk[8];
            float n3 = R3 * Rk[0] + R4 * Rk[3] + R5 * Rk[6];
            float n4 = R3 * Rk[1] + R4 * Rk[4] + R5 * Rk[7];
            float n5 = R3 * Rk[2] + R4 * Rk[5] + R5 * Rk[8];
            float n6 = R6 * Rk[0] + R7 * Rk[3] + R8 * Rk[6];
            float n7 = R6 * Rk[1] + R7 * Rk[4] + R8 * Rk[7];
            float n8 = R6 * Rk[2] + R7 * Rk[5] + R8 * Rk[8];
            R0 = n0; R1 = n1; R2 = n2; R3 = n3; R4 = n4; R5 = n5; R6 = n6; R7 = n7; R8 = n8;

            float Rax = R0 * ax + R1 * ay + R2 * az;
            float Ray = R3 * ax + R4 * ay + R5 * az;
            float Raz = R6 * ax + R7 * ay + R8 * az;

            // reference order: v updated first, p uses NEW v
            vx += Rax * DTF; vy += Ray * DTF; vz += Raz * DTF;
            px += vx * DTF + Rax * DT2H;
            py += vy * DTF + Ray * DT2H;
            pz += vz * DTF + Raz * DT2H;
        }
    }

    // ---------------- Block-level inclusive scan (Hillis-Steele, 8 rounds) --------------------
    float ndt = (float)PER * DTF;
    {
        float* me = sc[tid];
        me[0] = R0; me[1] = R1; me[2] = R2;
        me[3] = R3; me[4] = R4; me[5] = R5;
        me[6] = R6; me[7] = R7; me[8] = R8;
        me[9] = vx; me[10] = vy; me[11] = vz;
        me[12] = px; me[13] = py; me[14] = pz;
        me[15] = ndt;
    }
    __syncthreads();

    for (int d = 1; d < NTH; d <<= 1) {
        float lR[9], lvx, lvy, lvz, lpx, lpy, lpz, lndt;
        const bool act = (tid >= d);
        if (act) {
            const float* l = sc[tid - d];
            lR[0] = l[0]; lR[1] = l[1]; lR[2] = l[2];
            lR[3] = l[3]; lR[4] = l[4]; lR[5] = l[5];
            lR[6] = l[6]; lR[7] = l[7]; lR[8] = l[8];
            lvx = l[9]; lvy = l[10]; lvz = l[11];
            lpx = l[12]; lpy = l[13]; lpz = l[14];
            lndt = l[15];
        }
        __syncthreads();
        if (act) {
            // new = left (earlier) composed with mine (later)
            float t0 = lR[0] * R0 + lR[1] * R3 + lR[2] * R6;
            float t1 = lR[0] * R1 + lR[1] * R4 + lR[2] * R7;
            float t2 = lR[0] * R2 + lR[1] * R5 + lR[2] * R8;
            float t3 = lR[3] * R0 + lR[4] * R3 + lR[5] * R6;
            float t4 = lR[3] * R1 + lR[4] * R4 + lR[5] * R7;
            float t5 = lR[3] * R2 + lR[4] * R5 + lR[5] * R8;
            float t6 = lR[6] * R0 + lR[7] * R3 + lR[8] * R6;
            float t7 = lR[6] * R1 + lR[7] * R4 + lR[8] * R7;
            float t8 = lR[6] * R2 + lR[7] * R5 + lR[8] * R8;

            float nvx = lvx + lR[0] * vx + lR[1] * vy + lR[2] * vz;
            float nvy = lvy + lR[3] * vx + lR[4] * vy + lR[5] * vz;
            float nvz = lvz + lR[6] * vx + lR[7] * vy + lR[8] * vz;

            float npx = lpx + lvx * ndt + lR[0] * px + lR[1] * py + lR[2] * pz;
            float npy = lpy + lvy * ndt + lR[3] * px + lR[4] * py + lR[5] * pz;
            float npz = lpz + lvz * ndt + lR[6] * px + lR[7] * py + lR[8] * pz;

            R0 = t0; R1 = t1; R2 = t2; R3 = t3; R4 = t4; R5 = t5; R6 = t6; R7 = t7; R8 = t8;
            vx = nvx; vy = nvy; vz = nvz;
            px = npx; py = npy; pz = npz;
            ndt += lndt;

            float* me = sc[tid];
            me[0] = R0; me[1] = R1; me[2] = R2;
            me[3] = R3; me[4] = R4; me[5] = R5;
            me[6] = R6; me[7] = R7; me[8] = R8;
            me[9] = vx; me[10] = vy; me[11] = vz;
            me[12] = px; me[13] = py; me[14] = pz;
            me[15] = ndt;
        }
        __syncthreads();
    }

    // exclusive prefix for this thread = inclusive result of thread tid-1
    if (tid == 0) {
        R0 = 1.f; R1 = 0.f; R2 = 0.f;
        R3 = 0.f; R4 = 1.f; R5 = 0.f;
        R6 = 0.f; R7 = 0.f; R8 = 1.f;
        vx = vy = vz = 0.f;
        px = py = pz = 0.f;
    } else {
        const float* l = sc[tid - 1];
        R0 = l[0]; R1 = l[1]; R2 = l[2];
        R3 = l[3]; R4 = l[4]; R5 = l[5];
        R6 = l[6]; R7 = l[7]; R8 = l[8];
        vx = l[9]; vy = l[10]; vz = l[11];
        px = l[12]; py = l[13]; pz = l[14];
    }

    // ---------------- Phase 2: replay recurrence from prefix, emit outputs --------------------
    {
        const float* rp = rp0;
        float* op = out + ((size_t)b * T_LEN + (size_t)tid * PER) * 16;
#pragma unroll 2
        for (int k = 0; k < PER; k++) {
            float2 c0 = *(const float2*)(rp);
            float2 c1 = *(const float2*)(rp + 2);
            float2 c2 = *(const float2*)(rp + 4);
            rp += 6;
            float wx = c0.x, wy = c0.y, wz = c1.x;
            float ax = c1.y, ay = c2.x, az = c2.y;

            float Rk[9];
            make_Rk(wx, wy, wz, Rk);

            float n0 = R0 * Rk[0] + R1 * Rk[3] + R2 * Rk[6];
            float n1 = R0 * Rk[1] + R1 * Rk[4] + R2 * Rk[7];
            float n2 = R0 * Rk[2] + R1 * Rk[5] + R2 * Rk[8];
            float n3 = R3 * Rk[0] + R4 * Rk[3] + R5 * Rk[6];
            float n4 = R3 * Rk[1] + R4 * Rk[4] + R5 * Rk[7];
            float n5 = R3 * Rk[2] + R4 * Rk[5] + R5 * Rk[8];
            float n6 = R6 * Rk[0] + R7 * Rk[3] + R8 * Rk[6];
            float n7 = R6 * Rk[1] + R7 * Rk[4] + R8 * Rk[7];
            float n8 = R6 * Rk[2] + R7 * Rk[5] + R8 * Rk[8];
            R0 = n0; R1 = n1; R2 = n2; R3 = n3; R4 = n4; R5 = n5; R6 = n6; R7 = n7; R8 = n8;

            float Rax = R0 * ax + R1 * ay + R2 * az;
            float Ray = R3 * ax + R4 * ay + R5 * az;
            float Raz = R6 * ax + R7 * ay + R8 * az;

            vx += Rax * DTF; vy += Ray * DTF; vz += Raz * DTF;
            px += vx * DTF + Rax * DT2H;
            py += vy * DTF + Ray * DT2H;
            pz += vz * DTF + Raz * DT2H;

            // quaternion from R, matching reference clip + EPS behavior via half-angle identities
            float tr = R0 + R4 + R8;
            float c  = 0.5f * (tr - 1.0f);
            c = fminf(fmaxf(c, -1.0f + 1e-7f), 1.0f - 1e-7f);
            float t   = 0.5f * (1.0f + c);     // cos^2(half) in [5e-8, 1)
            float rin = rsqrtf(t);
            float qw  = t * rin;               // cos(half)
            float f   = 0.25f * rin;           // sin(half) / (2*sin(angle))
            float qx  = (R7 - R5) * f;
            float qy  = (R2 - R6) * f;
            float qz  = (R3 - R1) * f;

            float4* o4 = (float4*)op;
            o4[0] = make_float4(wx, wy, wz, ax);
            o4[1] = make_float4(ay, az, px, py);
            o4[2] = make_float4(pz, qw, qx, qy);
            o4[3] = make_float4(qz, vx, vy, vz);
            op += 16;
        }
    }
}

extern "C" void kernel_launch(void* const* d_in, const int* in_sizes, int n_in,
                              void* d_out, int out_size) {
    const float* in = (const float*)d_in[0];
    float* out = (float*)d_out;
    int Bn = in_sizes[0] / (T_LEN * 6);   // 512 for the reference shapes
    preint_kernel<<<Bn, NTH>>>(in, out);
}

// round 4
// speedup vs baseline: 1.5866x; 1.5866x over previous
#include <cuda_runtime.h>

#define T_LEN  4096
#define NTH    256
#define PER    16                 // steps per thread
#define TILE   2                  // steps per staging tile
#define NTILES (PER / TILE)       // 8
#define PITCH  257                // smem row pitch (floats), 257 % 32 == 1 -> conflict-free

#define DTF   (1.0f / 200.0f)
#define DT2H  (DTF * DTF * 0.5f)

struct Carry {
    float R0,R1,R2,R3,R4,R5,R6,R7,R8;
    float vx,vy,vz, px,py,pz;
};

// one recurrence step: R *= Rk(w);  Ra = R a;  v += Ra dt;  p += v dt + Ra dt^2/2
__device__ __forceinline__ void step_update(Carry& C,
                                            float wx, float wy, float wz,
                                            float ax, float ay, float az) {
    // Rodrigues via Taylor (theta <= ~0.03): R = I + A*K(w) + B*(w w^T - |w|^2 I)
    float n2  = fmaf(wx, wx, fmaf(wy, wy, wz * wz));
    float th2 = n2 * (DTF * DTF);
    float A   = DTF * (1.0f + th2 * (-1.0f / 6.0f + th2 * (1.0f / 120.0f)));
    float Bc  = (DTF * DTF) * (0.5f + th2 * (-1.0f / 24.0f + th2 * (1.0f / 720.0f)));
    float xy = wx * wy, xz = wx * wz, yz = wy * wz;
    float k0 = 1.0f + Bc * (wx * wx - n2);
    float k1 = Bc * xy - A * wz;
    float k2 = Bc * xz + A * wy;
    float k3 = Bc * xy + A * wz;
    float k4 = 1.0f + Bc * (wy * wy - n2);
    float k5 = Bc * yz - A * wx;
    float k6 = Bc * xz - A * wy;
    float k7 = Bc * yz + A * wx;
    float k8 = 1.0f + Bc * (wz * wz - n2);

    float n0 = C.R0*k0 + C.R1*k3 + C.R2*k6;
    float n1 = C.R0*k1 + C.R1*k4 + C.R2*k7;
    float n2_ = C.R0*k2 + C.R1*k5 + C.R2*k8;
    float n3 = C.R3*k0 + C.R4*k3 + C.R5*k6;
    float n4 = C.R3*k1 + C.R4*k4 + C.R5*k7;
    float n5 = C.R3*k2 + C.R4*k5 + C.R5*k8;
    float n6 = C.R6*k0 + C.R7*k3 + C.R8*k6;
    float n7 = C.R6*k1 + C.R7*k4 + C.R8*k7;
    float n8 = C.R6*k2 + C.R7*k5 + C.R8*k8;
    C.R0=n0; C.R1=n1; C.R2=n2_; C.R3=n3; C.R4=n4; C.R5=n5; C.R6=n6; C.R7=n7; C.R8=n8;

    float Rax = C.R0*ax + C.R1*ay + C.R2*az;
    float Ray = C.R3*ax + C.R4*ay + C.R5*az;
    float Raz = C.R6*ax + C.R7*ay + C.R8*az;

    C.vx += Rax * DTF; C.vy += Ray * DTF; C.vz += Raz * DTF;
    C.px += C.vx * DTF + Rax * DT2H;
    C.py += C.vy * DTF + Ray * DT2H;
    C.pz += C.vz * DTF + Raz * DT2H;
}

__global__ void __launch_bounds__(NTH, 4)
preint_kernel(const float* __restrict__ in, float* __restrict__ out) {
    // input staging: 12 rows (TILE*6) x 256 owners, transposed
    __shared__ float s_in[TILE * 6 * PITCH];          // 12*257 = 3084 floats
    // output staging: 32 rows (TILE*16) x 256 owners; also aliases the scan buffer
    __shared__ float s_out[TILE * 16 * PITCH];        // 32*257 = 8224 floats (>= 256*17)

    const int b   = blockIdx.x;
    const int tid = threadIdx.x;

    const float4* in4  = (const float4*)in + (size_t)b * (T_LEN * 6 / 4);
    float4*       out4 = (float4*)out      + (size_t)b * (T_LEN * 16 / 4);

    Carry C;
    C.R0=1.f; C.R1=0.f; C.R2=0.f; C.R3=0.f; C.R4=1.f; C.R5=0.f; C.R6=0.f; C.R7=0.f; C.R8=1.f;
    C.vx=C.vy=C.vz=0.f; C.px=C.py=C.pz=0.f;

    // ---------------- Phase 1: thread-local aggregate over PER steps (tiled) ----------------
#pragma unroll
    for (int tau = 0; tau < NTILES; tau++) {
        // cooperative fill: 768 float4 per tile, owner o's tile chunk = 3 float4 at o*24 + tau*3
#pragma unroll
        for (int r = 0; r < 3; r++) {
            int f  = tid + NTH * r;
            int o  = f / 3;
            int jq = f - o * 3;
            float4 v = in4[(size_t)o * 24 + tau * 3 + jq];
            int row = jq * 4;
            s_in[(row + 0) * PITCH + o] = v.x;
            s_in[(row + 1) * PITCH + o] = v.y;
            s_in[(row + 2) * PITCH + o] = v.z;
            s_in[(row + 3) * PITCH + o] = v.w;
        }
        __syncthreads();
#pragma unroll
        for (int k = 0; k < TILE; k++) {
            float wx = s_in[(k*6 + 0) * PITCH + tid];
            float wy = s_in[(k*6 + 1) * PITCH + tid];
            float wz = s_in[(k*6 + 2) * PITCH + tid];
            float ax = s_in[(k*6 + 3) * PITCH + tid];
            float ay = s_in[(k*6 + 4) * PITCH + tid];
            float az = s_in[(k*6 + 5) * PITCH + tid];
            step_update(C, wx, wy, wz, ax, ay, az);
        }
        __syncthreads();
    }

    // ---------------- Block-level inclusive scan (Hillis-Steele over 256 threads) -----------
    // scan element: (R9, v3, p3, ndt) = 16 floats, stride-17 rows inside s_out
    float ndt = (float)PER * DTF;
    {
        float* me = s_out + tid * 17;
        me[0]=C.R0; me[1]=C.R1; me[2]=C.R2; me[3]=C.R3; me[4]=C.R4; me[5]=C.R5;
        me[6]=C.R6; me[7]=C.R7; me[8]=C.R8;
        me[9]=C.vx; me[10]=C.vy; me[11]=C.vz;
        me[12]=C.px; me[13]=C.py; me[14]=C.pz;
        me[15]=ndt;
    }
    __syncthreads();

    for (int d = 1; d < NTH; d <<= 1) {
        float lR[9], lvx, lvy, lvz, lpx, lpy, lpz, lndt;
        const bool act = (tid >= d);
        if (act) {
            const float* l = s_out + (tid - d) * 17;
            lR[0]=l[0]; lR[1]=l[1]; lR[2]=l[2]; lR[3]=l[3]; lR[4]=l[4]; lR[5]=l[5];
            lR[6]=l[6]; lR[7]=l[7]; lR[8]=l[8];
            lvx=l[9]; lvy=l[10]; lvz=l[11];
            lpx=l[12]; lpy=l[13]; lpz=l[14]; lndt=l[15];
        }
        __syncthreads();
        if (act) {
            float t0 = lR[0]*C.R0 + lR[1]*C.R3 + lR[2]*C.R6;
            float t1 = lR[0]*C.R1 + lR[1]*C.R4 + lR[2]*C.R7;
            float t2 = lR[0]*C.R2 + lR[1]*C.R5 + lR[2]*C.R8;
            float t3 = lR[3]*C.R0 + lR[4]*C.R3 + lR[5]*C.R6;
            float t4 = lR[3]*C.R1 + lR[4]*C.R4 + lR[5]*C.R7;
            float t5 = lR[3]*C.R2 + lR[4]*C.R5 + lR[5]*C.R8;
            float t6 = lR[6]*C.R0 + lR[7]*C.R3 + lR[8]*C.R6;
            float t7 = lR[6]*C.R1 + lR[7]*C.R4 + lR[8]*C.R7;
            float t8 = lR[6]*C.R2 + lR[7]*C.R5 + lR[8]*C.R8;

            float nvx = lvx + lR[0]*C.vx + lR[1]*C.vy + lR[2]*C.vz;
            float nvy = lvy + lR[3]*C.vx + lR[4]*C.vy + lR[5]*C.vz;
            float nvz = lvz + lR[6]*C.vx + lR[7]*C.vy + lR[8]*C.vz;

            float npx = lpx + lvx*ndt + lR[0]*C.px + lR[1]*C.py + lR[2]*C.pz;
            float npy = lpy + lvy*ndt + lR[3]*C.px + lR[4]*C.py + lR[5]*C.pz;
            float npz = lpz + lvz*ndt + lR[6]*C.px + lR[7]*C.py + lR[8]*C.pz;

            C.R0=t0; C.R1=t1; C.R2=t2; C.R3=t3; C.R4=t4; C.R5=t5; C.R6=t6; C.R7=t7; C.R8=t8;
            C.vx=nvx; C.vy=nvy; C.vz=nvz;
            C.px=npx; C.py=npy; C.pz=npz;
            ndt += lndt;

            float* me = s_out + tid * 17;
            me[0]=C.R0; me[1]=C.R1; me[2]=C.R2; me[3]=C.R3; me[4]=C.R4; me[5]=C.R5;
            me[6]=C.R6; me[7]=C.R7; me[8]=C.R8;
            me[9]=C.vx; me[10]=C.vy; me[11]=C.vz;
            me[12]=C.px; me[13]=C.py; me[14]=C.pz;
            me[15]=ndt;
        }
        __syncthreads();
    }

    // exclusive prefix = inclusive of tid-1 (pulled to registers BEFORE s_out is reused)
    if (tid == 0) {
        C.R0=1.f; C.R1=0.f; C.R2=0.f; C.R3=0.f; C.R4=1.f; C.R5=0.f; C.R6=0.f; C.R7=0.f; C.R8=1.f;
        C.vx=C.vy=C.vz=0.f; C.px=C.py=C.pz=0.f;
    } else {
        const float* l = s_out + (tid - 1) * 17;
        C.R0=l[0]; C.R1=l[1]; C.R2=l[2]; C.R3=l[3]; C.R4=l[4]; C.R5=l[5];
        C.R6=l[6]; C.R7=l[7]; C.R8=l[8];
        C.vx=l[9]; C.vy=l[10]; C.vz=l[11];
        C.px=l[12]; C.py=l[13]; C.pz=l[14];
    }
    // (next __syncthreads inside the tile loop orders these reads before s_out writes)

    // ---------------- Phase 2: replay with prefix, staged + coalesced output ----------------
#pragma unroll
    for (int tau = 0; tau < NTILES; tau++) {
        // fill input tile (same as phase 1)
#pragma unroll
        for (int r = 0; r < 3; r++) {
            int f  = tid + NTH * r;
            int o  = f / 3;
            int jq = f - o * 3;
            float4 v = in4[(size_t)o * 24 + tau * 3 + jq];
            int row = jq * 4;
            s_in[(row + 0) * PITCH + o] = v.x;
            s_in[(row + 1) * PITCH + o] = v.y;
            s_in[(row + 2) * PITCH + o] = v.z;
            s_in[(row + 3) * PITCH + o] = v.w;
        }
        __syncthreads();

#pragma unroll
        for (int k = 0; k < TILE; k++) {
            float wx = s_in[(k*6 + 0) * PITCH + tid];
            float wy = s_in[(k*6 + 1) * PITCH + tid];
            float wz = s_in[(k*6 + 2) * PITCH + tid];
            float ax = s_in[(k*6 + 3) * PITCH + tid];
            float ay = s_in[(k*6 + 4) * PITCH + tid];
            float az = s_in[(k*6 + 5) * PITCH + tid];

            step_update(C, wx, wy, wz, ax, ay, az);

            // quaternion from R (half-angle identities, matches reference clip+EPS path)
            float tr = C.R0 + C.R4 + C.R8;
            float cc = 0.5f * (tr - 1.0f);
            cc = fminf(fmaxf(cc, -1.0f + 1e-7f), 1.0f - 1e-7f);
            float t   = 0.5f * (1.0f + cc);
            float rin = rsqrtf(t);
            float qw  = t * rin;
            float fq  = 0.25f * rin;
            float qx  = (C.R7 - C.R5) * fq;
            float qy  = (C.R2 - C.R6) * fq;
            float qz  = (C.R3 - C.R1) * fq;

            float* d = s_out + (k * 16) * PITCH + tid;
            d[0*PITCH]  = wx;   d[1*PITCH]  = wy;   d[2*PITCH]  = wz;
            d[3*PITCH]  = ax;   d[4*PITCH]  = ay;   d[5*PITCH]  = az;
            d[6*PITCH]  = C.px; d[7*PITCH]  = C.py; d[8*PITCH]  = C.pz;
            d[9*PITCH]  = qw;   d[10*PITCH] = qx;   d[11*PITCH] = qy;
            d[12*PITCH] = qz;
            d[13*PITCH] = C.vx; d[14*PITCH] = C.vy; d[15*PITCH] = C.vz;
        }
        __syncthreads();

        // coalesced flush: 2048 float4 per tile; each warp instr covers 4 full 128B lines
#pragma unroll
        for (int r = 0; r < 8; r++) {
            int f  = tid + NTH * r;
            int o  = f >> 3;
            int mq = f & 7;
            const float* srow = s_out + (mq * 4) * PITCH + o;
            float4 v = make_float4(srow[0*PITCH], srow[1*PITCH], srow[2*PITCH], srow[3*PITCH]);
            out4[(size_t)o * 64 + tau * 8 + mq] = v;
        }
        __syncthreads();
    }
}

extern "C" void kernel_launch(void* const* d_in, const int* in_sizes, int n_in,
                              void* d_out, int out_size) {
    const float* in = (const float*)d_in[0];
    float* out = (float*)d_out;
    int Bn = in_sizes[0] / (T_LEN * 6);   // 512 for the reference shapes
    preint_kernel<<<Bn, NTH>>>(in, out);
}